// round 1
// baseline (speedup 1.0000x reference)
#include <cuda_runtime.h>
#include <cuda_bf16.h>
#include <math.h>

// Problem constants
#define B_    256
#define S_    20
#define V_    20000
#define C_    20
#define D_    64
#define SUPROWS 5120          // B_*S_
#define MROWS   5376          // SUPROWS + B_
#define KSPLIT  7
#define CHUNKS  625           // V_/32

// Scratch (allocation-free rule: __device__ globals)
__device__ float g_Yp[KSPLIT * MROWS * D_];   // K-split partial projections
__device__ float g_res[2 * B_];               // per-batch (correct, loss)

__device__ __forceinline__ unsigned long long pack2(float x) {
    unsigned long long r;
    asm("mov.b64 %0, {%1, %1};" : "=l"(r) : "f"(x));
    return r;
}
__device__ __forceinline__ void ffma2(unsigned long long& d,
                                      unsigned long long a,
                                      unsigned long long b) {
    asm("fma.rn.f32x2 %0, %1, %2, %0;" : "+l"(d) : "l"(a), "l"(b));
}
__device__ __forceinline__ void unpack2(unsigned long long v, float& lo, float& hi) {
    asm("mov.b64 {%0, %1}, %2;" : "=f"(lo), "=f"(hi) : "l"(v));
}

// ---------------------------------------------------------------------------
// GEMM: Y[row, d] = sum_v X[row, v] * W[d, v]
// rows 0..5119 -> support_set_images, rows 5120..5375 -> target_image
// Grid: (84 row-tiles of 64, KSPLIT).  Partials to g_Yp[by].
// ---------------------------------------------------------------------------
__global__ __launch_bounds__(256)
void gemm_kernel(const float* __restrict__ sup,
                 const float* __restrict__ tgt,
                 const float* __restrict__ W) {
    __shared__ float As[32][64];   // [k][row]
    __shared__ float Ws[32][64];   // [k][d]

    const int tid = threadIdx.x;
    const int rowbase = blockIdx.x * 64;
    const int by = blockIdx.y;
    const int c0 = (by * CHUNKS) / KSPLIT;
    const int c1 = ((by + 1) * CHUNKS) / KSPLIT;

    // loader mapping: one row/d per thread-quarter, conflict-free transposed stores
    const int lr = tid & 63;
    const int q  = tid >> 6;          // 0..3
    const int grow = rowbase + lr;
    const float* arow = (grow < SUPROWS)
                        ? (sup + (size_t)grow * V_)
                        : (tgt + (size_t)(grow - SUPROWS) * V_);
    const float* wrow = W + (size_t)lr * V_;

    // compute mapping: 16x16 threads, 4 rows x 4 cols each
    const int tx = tid & 15;          // col group: cols 4*tx..4*tx+3
    const int ty = tid >> 4;          // row group: rows 4*ty..4*ty+3

    unsigned long long acc[2][4] = {};   // [rowpair][col], f32x2 = (row lo, row hi)

    for (int c = c0; c < c1; ++c) {
        const int k0 = c * 32;
        float4 av0 = *(const float4*)(arow + k0 + 4 * q);
        float4 av1 = *(const float4*)(arow + k0 + 16 + 4 * q);
        float4 wv0 = *(const float4*)(wrow + k0 + 4 * q);
        float4 wv1 = *(const float4*)(wrow + k0 + 16 + 4 * q);
        __syncthreads();   // previous compute done before overwrite
        As[4 * q + 0][lr] = av0.x; As[4 * q + 1][lr] = av0.y;
        As[4 * q + 2][lr] = av0.z; As[4 * q + 3][lr] = av0.w;
        As[16 + 4 * q + 0][lr] = av1.x; As[16 + 4 * q + 1][lr] = av1.y;
        As[16 + 4 * q + 2][lr] = av1.z; As[16 + 4 * q + 3][lr] = av1.w;
        Ws[4 * q + 0][lr] = wv0.x; Ws[4 * q + 1][lr] = wv0.y;
        Ws[4 * q + 2][lr] = wv0.z; Ws[4 * q + 3][lr] = wv0.w;
        Ws[16 + 4 * q + 0][lr] = wv1.x; Ws[16 + 4 * q + 1][lr] = wv1.y;
        Ws[16 + 4 * q + 2][lr] = wv1.z; Ws[16 + 4 * q + 3][lr] = wv1.w;
        __syncthreads();

        #pragma unroll 8
        for (int k = 0; k < 32; ++k) {
            unsigned long long a01 = *(const unsigned long long*)&As[k][4 * ty];
            unsigned long long a23 = *(const unsigned long long*)&As[k][4 * ty + 2];
            float4 w = *(const float4*)&Ws[k][4 * tx];
            unsigned long long w0 = pack2(w.x), w1 = pack2(w.y),
                               w2 = pack2(w.z), w3 = pack2(w.w);
            ffma2(acc[0][0], a01, w0); ffma2(acc[1][0], a23, w0);
            ffma2(acc[0][1], a01, w1); ffma2(acc[1][1], a23, w1);
            ffma2(acc[0][2], a01, w2); ffma2(acc[1][2], a23, w2);
            ffma2(acc[0][3], a01, w3); ffma2(acc[1][3], a23, w3);
        }
    }

    // epilogue: acc[p][j] = (row 4ty+2p col 4tx+j, row 4ty+2p+1 col 4tx+j)
    float* yp = g_Yp + ((size_t)by * MROWS + rowbase) * D_;
    #pragma unroll
    for (int p = 0; p < 2; ++p) {
        float lo[4], hi[4];
        #pragma unroll
        for (int j = 0; j < 4; ++j) unpack2(acc[p][j], lo[j], hi[j]);
        float4 vlo = make_float4(lo[0], lo[1], lo[2], lo[3]);
        float4 vhi = make_float4(hi[0], hi[1], hi[2], hi[3]);
        *(float4*)(yp + (size_t)(4 * ty + 2 * p) * D_ + 4 * tx) = vlo;
        *(float4*)(yp + (size_t)(4 * ty + 2 * p + 1) * D_ + 4 * tx) = vhi;
    }
}

// ---------------------------------------------------------------------------
// Head: one warp per batch element. Sum K-split partials + bias, compute
// similarities, softmax attention, preds, argmax (first-index tiebreak), CE.
// ---------------------------------------------------------------------------
__global__ __launch_bounds__(32)
void head_kernel(const float* __restrict__ onehot,
                 const int* __restrict__ tylab,
                 const float* __restrict__ bias) {
    const int b = blockIdx.x;
    const int lane = threadIdx.x;
    const unsigned FULL = 0xffffffffu;

    const float b0 = bias[lane], b1 = bias[lane + 32];

    // target embedding (2 dims per lane)
    const int trow = SUPROWS + b;
    float tg0 = b0, tg1 = b1;
    #pragma unroll
    for (int p = 0; p < KSPLIT; ++p) {
        const float* r = g_Yp + ((size_t)p * MROWS + trow) * D_;
        tg0 += r[lane]; tg1 += r[lane + 32];
    }

    float sims[S_];
    #pragma unroll
    for (int s = 0; s < S_; ++s) {
        const int row = b * S_ + s;
        float v0 = b0, v1 = b1;
        #pragma unroll
        for (int p = 0; p < KSPLIT; ++p) {
            const float* r = g_Yp + ((size_t)p * MROWS + row) * D_;
            v0 += r[lane]; v1 += r[lane + 32];
        }
        float dot = v0 * tg0 + v1 * tg1;
        float nrm = v0 * v0 + v1 * v1;
        #pragma unroll
        for (int o = 16; o > 0; o >>= 1) {
            dot += __shfl_xor_sync(FULL, dot, o);
            nrm += __shfl_xor_sync(FULL, nrm, o);
        }
        sims[s] = dot * rsqrtf(fmaxf(nrm, 1e-10f));
    }

    // softmax over support dimension (replicated across lanes)
    float m = sims[0];
    #pragma unroll
    for (int s = 1; s < S_; ++s) m = fmaxf(m, sims[s]);
    float e[S_];
    float den = 0.f;
    #pragma unroll
    for (int s = 0; s < S_; ++s) { e[s] = expf(sims[s] - m); den += e[s]; }
    const float inv = 1.f / den;

    // preds: lane c < 20 owns class c
    float pred = 0.f;
    if (lane < C_) {
        #pragma unroll
        for (int s = 0; s < S_; ++s)
            pred += e[s] * inv * onehot[((size_t)b * S_ + s) * C_ + lane];
    }

    // reductions over valid lanes
    float pv = (lane < C_) ? pred : -3.0e38f;
    float pm = pv;
    #pragma unroll
    for (int o = 16; o > 0; o >>= 1) pm = fmaxf(pm, __shfl_xor_sync(FULL, pm, o));
    float ex = (lane < C_) ? expf(pred - pm) : 0.f;
    float se = ex;
    #pragma unroll
    for (int o = 16; o > 0; o >>= 1) se += __shfl_xor_sync(FULL, se, o);
    const float lse = pm + logf(se);

    // argmax with smallest-index tiebreak (matches jnp.argmax)
    float av = pv;
    int ai = lane;
    #pragma unroll
    for (int o = 16; o > 0; o >>= 1) {
        float ov = __shfl_xor_sync(FULL, av, o);
        int oi = __shfl_xor_sync(FULL, ai, o);
        if (ov > av || (ov == av && oi < ai)) { av = ov; ai = oi; }
    }

    const int t = tylab[b];
    const float pt = __shfl_sync(FULL, pred, t);
    if (lane == 0) {
        g_res[b] = (ai == t) ? 1.f : 0.f;
        g_res[B_ + b] = -(pt - lse);
    }
}

// ---------------------------------------------------------------------------
// Final fixed-order reduction -> d_out[0]=accuracy, d_out[1]=loss
// ---------------------------------------------------------------------------
__global__ __launch_bounds__(256)
void reduce_kernel(float* __restrict__ out) {
    __shared__ float s0[B_], s1[B_];
    const int t = threadIdx.x;
    s0[t] = g_res[t];
    s1[t] = g_res[B_ + t];
    __syncthreads();
    #pragma unroll
    for (int o = 128; o > 0; o >>= 1) {
        if (t < o) { s0[t] += s0[t + o]; s1[t] += s1[t + o]; }
        __syncthreads();
    }
    if (t == 0) {
        out[0] = s0[0] * (1.f / B_);
        out[1] = s1[0] * (1.f / B_);
    }
}

extern "C" void kernel_launch(void* const* d_in, const int* in_sizes, int n_in,
                              void* d_out, int out_size) {
    const float* sup    = (const float*)d_in[0];
    const float* onehot = (const float*)d_in[1];
    const float* tgt    = (const float*)d_in[2];
    const int*   tylab  = (const int*)d_in[3];
    const float* W      = (const float*)d_in[4];
    const float* bias   = (const float*)d_in[5];
    (void)in_sizes; (void)n_in; (void)out_size;

    dim3 grid(MROWS / 64, KSPLIT);
    gemm_kernel<<<grid, 256>>>(sup, tgt, W);
    head_kernel<<<B_, 32>>>(onehot, tylab, bias);
    reduce_kernel<<<1, 256>>>((float*)d_out);
}

// round 2
// speedup vs baseline: 1.1044x; 1.1044x over previous
#include <cuda_runtime.h>
#include <cuda_bf16.h>
#include <math.h>

// Problem constants
#define B_    256
#define S_    20
#define V_    20000
#define C_    20
#define D_    64
#define SUPROWS 5120          // B_*S_
#define MROWS   5376          // SUPROWS + B_
#define KSPLIT  7
#define KCH     8             // k's per chunk
#define NCH     2500          // V_/KCH
#define TILE_R  128

typedef unsigned long long ull;

// Scratch (allocation-free rule: __device__ globals)
__device__ float g_Yp[KSPLIT * MROWS * D_];   // K-split partial projections
__device__ float g_res[2 * B_];               // per-batch (correct, loss)

__device__ __forceinline__ ull pack2(float x) {
    ull r;
    asm("mov.b64 %0, {%1, %1};" : "=l"(r) : "f"(x));
    return r;
}
__device__ __forceinline__ void ffma2(ull& d, ull a, ull b) {
    asm("fma.rn.f32x2 %0, %1, %2, %0;" : "+l"(d) : "l"(a), "l"(b));
}
__device__ __forceinline__ void unpack2(ull v, float& lo, float& hi) {
    asm("mov.b64 {%0, %1}, %2;" : "=f"(lo), "=f"(hi) : "l"(v));
}

// ---------------------------------------------------------------------------
// GEMM: Y[row, d] = sum_v X[row, v] * W[d, v]
// Tile: 128 rows x 64 cols, 256 threads, 4 rows x 8 cols per thread.
// Software-pipelined double-buffered smem, FFMA2 accumulators paired over cols.
// ---------------------------------------------------------------------------
__global__ __launch_bounds__(256)
void gemm_kernel(const float* __restrict__ sup,
                 const float* __restrict__ tgt,
                 const float* __restrict__ W) {
    __shared__ float As[2][KCH][TILE_R];   // [buf][k][row]
    __shared__ float Ws[2][KCH][72];       // [buf][k][dpad], 4-float pad at col 32

    const int tid = threadIdx.x;
    const int rowbase = blockIdx.x * TILE_R;
    const int by = blockIdx.y;
    const int c0 = (by * NCH) / KSPLIT;
    const int c1 = ((by + 1) * NCH) / KSPLIT;

    // --- loader mapping ---
    // A: thread -> (row = tid&127, half = tid>>7), loads 4 floats of that row
    const int ar = tid & 127;
    const int ah = tid >> 7;            // 0/1 -> k offset 0/4
    const int grow = rowbase + ar;
    const float* arow = (grow < SUPROWS)
                        ? (sup + (size_t)grow * V_)
                        : (tgt + (size_t)(grow - SUPROWS) * V_);
    // W: threads 0..127 -> (d = tid&63, half = (tid>>6)&1)
    const int wd = tid & 63;
    const int wh = (tid >> 6) & 1;
    const int wdp = wd + ((wd & 32) >> 3);      // +4 pad for upper half
    const float* wrow = W + (size_t)wd * V_;
    const bool wload = (tid < 128);

    // --- compute mapping: tx = col group (8 cols), ty = row group (4 rows) ---
    const int tx = tid & 7;
    const int ty = tid >> 3;
    const int wbase = 8 * tx + (tx >= 4 ? 4 : 0);   // padded W column base

    ull acc[4][4] = {};   // [row r][col pair jp] ; pair = cols (8tx+2jp, 8tx+2jp+1)

    // --- prologue: load + stage chunk c0 ---
    float4 av = *(const float4*)(arow + c0 * KCH + 4 * ah);
    float4 wv = make_float4(0.f, 0.f, 0.f, 0.f);
    if (wload) wv = *(const float4*)(wrow + c0 * KCH + 4 * wh);

    {
        const int ks = 4 * ah;
        As[0][ks + 0][ar] = av.x; As[0][ks + 1][ar] = av.y;
        As[0][ks + 2][ar] = av.z; As[0][ks + 3][ar] = av.w;
        if (wload) {
            const int kw = 4 * wh;
            Ws[0][kw + 0][wdp] = wv.x; Ws[0][kw + 1][wdp] = wv.y;
            Ws[0][kw + 2][wdp] = wv.z; Ws[0][kw + 3][wdp] = wv.w;
        }
    }
    __syncthreads();

    int buf = 0;
    for (int c = c0; c < c1; ++c) {
        const bool more = (c + 1 < c1);
        if (more) {
            av = *(const float4*)(arow + (c + 1) * KCH + 4 * ah);
            if (wload) wv = *(const float4*)(wrow + (c + 1) * KCH + 4 * wh);
        }

        #pragma unroll
        for (int k = 0; k < KCH; ++k) {
            float4 a = *(const float4*)&As[buf][k][4 * ty];
            ulonglong2 w01 = *(const ulonglong2*)&Ws[buf][k][wbase];
            ulonglong2 w23 = *(const ulonglong2*)&Ws[buf][k][wbase + 4];
            ull a0 = pack2(a.x), a1 = pack2(a.y), a2 = pack2(a.z), a3 = pack2(a.w);
            ffma2(acc[0][0], a0, w01.x); ffma2(acc[0][1], a0, w01.y);
            ffma2(acc[0][2], a0, w23.x); ffma2(acc[0][3], a0, w23.y);
            ffma2(acc[1][0], a1, w01.x); ffma2(acc[1][1], a1, w01.y);
            ffma2(acc[1][2], a1, w23.x); ffma2(acc[1][3], a1, w23.y);
            ffma2(acc[2][0], a2, w01.x); ffma2(acc[2][1], a2, w01.y);
            ffma2(acc[2][2], a2, w23.x); ffma2(acc[2][3], a2, w23.y);
            ffma2(acc[3][0], a3, w01.x); ffma2(acc[3][1], a3, w01.y);
            ffma2(acc[3][2], a3, w23.x); ffma2(acc[3][3], a3, w23.y);
        }

        if (more) {
            const int nb = buf ^ 1;
            const int ks = 4 * ah;
            As[nb][ks + 0][ar] = av.x; As[nb][ks + 1][ar] = av.y;
            As[nb][ks + 2][ar] = av.z; As[nb][ks + 3][ar] = av.w;
            if (wload) {
                const int kw = 4 * wh;
                Ws[nb][kw + 0][wdp] = wv.x; Ws[nb][kw + 1][wdp] = wv.y;
                Ws[nb][kw + 2][wdp] = wv.z; Ws[nb][kw + 3][wdp] = wv.w;
            }
        }
        __syncthreads();
        buf ^= 1;
    }

    // --- epilogue ---
    float* yp = g_Yp + ((size_t)by * MROWS + rowbase) * D_;
    #pragma unroll
    for (int r = 0; r < 4; ++r) {
        float c[8];
        #pragma unroll
        for (int jp = 0; jp < 4; ++jp) unpack2(acc[r][jp], c[2 * jp], c[2 * jp + 1]);
        float* dst = yp + (size_t)(4 * ty + r) * D_ + 8 * tx;
        *(float4*)(dst)     = make_float4(c[0], c[1], c[2], c[3]);
        *(float4*)(dst + 4) = make_float4(c[4], c[5], c[6], c[7]);
    }
}

// ---------------------------------------------------------------------------
// Head: one warp per batch element. Sum K-split partials + bias, compute
// similarities, softmax attention, preds, argmax (first-index tiebreak), CE.
// ---------------------------------------------------------------------------
__global__ __launch_bounds__(32)
void head_kernel(const float* __restrict__ onehot,
                 const int* __restrict__ tylab,
                 const float* __restrict__ bias) {
    const int b = blockIdx.x;
    const int lane = threadIdx.x;
    const unsigned FULL = 0xffffffffu;

    const float b0 = bias[lane], b1 = bias[lane + 32];

    const int trow = SUPROWS + b;
    float tg0 = b0, tg1 = b1;
    #pragma unroll
    for (int p = 0; p < KSPLIT; ++p) {
        const float* r = g_Yp + ((size_t)p * MROWS + trow) * D_;
        tg0 += r[lane]; tg1 += r[lane + 32];
    }

    float sims[S_];
    #pragma unroll
    for (int s = 0; s < S_; ++s) {
        const int row = b * S_ + s;
        float v0 = b0, v1 = b1;
        #pragma unroll
        for (int p = 0; p < KSPLIT; ++p) {
            const float* r = g_Yp + ((size_t)p * MROWS + row) * D_;
            v0 += r[lane]; v1 += r[lane + 32];
        }
        float dot = v0 * tg0 + v1 * tg1;
        float nrm = v0 * v0 + v1 * v1;
        #pragma unroll
        for (int o = 16; o > 0; o >>= 1) {
            dot += __shfl_xor_sync(FULL, dot, o);
            nrm += __shfl_xor_sync(FULL, nrm, o);
        }
        sims[s] = dot * rsqrtf(fmaxf(nrm, 1e-10f));
    }

    float m = sims[0];
    #pragma unroll
    for (int s = 1; s < S_; ++s) m = fmaxf(m, sims[s]);
    float e[S_];
    float den = 0.f;
    #pragma unroll
    for (int s = 0; s < S_; ++s) { e[s] = expf(sims[s] - m); den += e[s]; }
    const float inv = 1.f / den;

    float pred = 0.f;
    if (lane < C_) {
        #pragma unroll
        for (int s = 0; s < S_; ++s)
            pred += e[s] * inv * onehot[((size_t)b * S_ + s) * C_ + lane];
    }

    float pv = (lane < C_) ? pred : -3.0e38f;
    float pm = pv;
    #pragma unroll
    for (int o = 16; o > 0; o >>= 1) pm = fmaxf(pm, __shfl_xor_sync(FULL, pm, o));
    float ex = (lane < C_) ? expf(pred - pm) : 0.f;
    float se = ex;
    #pragma unroll
    for (int o = 16; o > 0; o >>= 1) se += __shfl_xor_sync(FULL, se, o);
    const float lse = pm + logf(se);

    float av = pv;
    int ai = lane;
    #pragma unroll
    for (int o = 16; o > 0; o >>= 1) {
        float ov = __shfl_xor_sync(FULL, av, o);
        int oi = __shfl_xor_sync(FULL, ai, o);
        if (ov > av || (ov == av && oi < ai)) { av = ov; ai = oi; }
    }

    const int t = tylab[b];
    const float pt = __shfl_sync(FULL, pred, t);
    if (lane == 0) {
        g_res[b] = (ai == t) ? 1.f : 0.f;
        g_res[B_ + b] = -(pt - lse);
    }
}

// ---------------------------------------------------------------------------
// Final fixed-order reduction -> d_out[0]=accuracy, d_out[1]=loss
// ---------------------------------------------------------------------------
__global__ __launch_bounds__(256)
void reduce_kernel(float* __restrict__ out) {
    __shared__ float s0[B_], s1[B_];
    const int t = threadIdx.x;
    s0[t] = g_res[t];
    s1[t] = g_res[B_ + t];
    __syncthreads();
    #pragma unroll
    for (int o = 128; o > 0; o >>= 1) {
        if (t < o) { s0[t] += s0[t + o]; s1[t] += s1[t + o]; }
        __syncthreads();
    }
    if (t == 0) {
        out[0] = s0[0] * (1.f / B_);
        out[1] = s1[0] * (1.f / B_);
    }
}

extern "C" void kernel_launch(void* const* d_in, const int* in_sizes, int n_in,
                              void* d_out, int out_size) {
    const float* sup    = (const float*)d_in[0];
    const float* onehot = (const float*)d_in[1];
    const float* tgt    = (const float*)d_in[2];
    const int*   tylab  = (const int*)d_in[3];
    const float* W      = (const float*)d_in[4];
    const float* bias   = (const float*)d_in[5];
    (void)in_sizes; (void)n_in; (void)out_size;

    dim3 grid(MROWS / TILE_R, KSPLIT);
    gemm_kernel<<<grid, 256>>>(sup, tgt, W);
    head_kernel<<<B_, 32>>>(onehot, tylab, bias);
    reduce_kernel<<<1, 256>>>((float*)d_out);
}

// round 4
// speedup vs baseline: 2.1874x; 1.9805x over previous
#include <cuda_runtime.h>
#include <cuda_bf16.h>
#include <math.h>
#include <stdint.h>

// Problem constants
#define B_    256
#define S_    20
#define V_    20000
#define C_    20
#define D_    64
#define SUPROWS 5120          // B_*S_
#define MROWS   5376          // SUPROWS + B_
#define KSPLIT  7
#define NCHUNK  313           // ceil(20000/64); last chunk has 32 valid k
#define TILE_R  128

// Scratch (allocation-free rule: __device__ globals)
__device__ float g_Yp[KSPLIT * MROWS * D_];   // K-split partial projections
__device__ float g_res[2 * B_];               // per-batch (correct, loss)

// ---- smem layout (dynamic), per buffer: A_hi 16K | A_lo 16K | W_hi 8K | W_lo 8K
#define BUF_STRIDE 49152
#define A_HI_OFF   0
#define A_LO_OFF   16384
#define W_HI_OFF   32768
#define W_LO_OFF   40960
#define SMEM_TOTAL (2 * BUF_STRIDE)

__device__ __forceinline__ uint32_t smem_u32(const void* p) {
    uint32_t a;
    asm("{ .reg .u64 t; cvta.to.shared.u64 t, %1; cvt.u32.u64 %0, t; }" : "=r"(a) : "l"(p));
    return a;
}
// hi-pack: bf16x2 from truncated top halves of two f32 (low elem from a)
__device__ __forceinline__ uint32_t prmt_hi(float a, float b) {
    uint32_t r;
    asm("prmt.b32 %0, %1, %2, 0x7632;" : "=r"(r) : "r"(__float_as_uint(a)), "r"(__float_as_uint(b)));
    return r;
}
__device__ __forceinline__ float trunc_hi(float x) {
    return __uint_as_float(__float_as_uint(x) & 0xffff0000u);
}
// lo-pack: bf16x2 rn of residuals; low elem from a
__device__ __forceinline__ uint32_t pack_lo(float a, float b) {
    float la = a - trunc_hi(a);
    float lb = b - trunc_hi(b);
    uint32_t r;
    asm("cvt.rn.bf16x2.f32 %0, %1, %2;" : "=r"(r) : "f"(lb), "f"(la));
    return r;
}
__device__ __forceinline__ void ldsm4(uint32_t* r, uint32_t addr) {
    asm volatile("ldmatrix.sync.aligned.m8n8.x4.shared.b16 {%0,%1,%2,%3}, [%4];"
                 : "=r"(r[0]), "=r"(r[1]), "=r"(r[2]), "=r"(r[3]) : "r"(addr));
}
__device__ __forceinline__ void mma_bf16(float* d, const uint32_t* a, const uint32_t* b) {
    asm volatile(
        "mma.sync.aligned.m16n8k16.row.col.f32.bf16.bf16.f32 "
        "{%0,%1,%2,%3}, {%4,%5,%6,%7}, {%8,%9}, {%0,%1,%2,%3};"
        : "+f"(d[0]), "+f"(d[1]), "+f"(d[2]), "+f"(d[3])
        : "r"(a[0]), "r"(a[1]), "r"(a[2]), "r"(a[3]), "r"(b[0]), "r"(b[1]));
}

// ---------------------------------------------------------------------------
// GEMM via HMMA bf16-split (hi*hi + hi*lo + lo*hi), fp32 register accumulate.
// Tile 128 rows x 64 cols; K chunks of 64; 8 warps each own 32r x 32c.
// ---------------------------------------------------------------------------
__global__ __launch_bounds__(256)
void gemm_kernel(const float* __restrict__ sup,
                 const float* __restrict__ tgt,
                 const float* __restrict__ W) {
    extern __shared__ char smem[];
    const uint32_t sb = smem_u32(smem);
    const int tid = threadIdx.x;
    const int wid = tid >> 5;
    const int lane = tid & 31;
    const int wr = wid >> 1;          // warp row group: rows 32*wr
    const int wc = wid & 1;           // warp col group: cols 32*wc
    const int rowbase = blockIdx.x * TILE_R;
    const int by = blockIdx.y;

    const int c0 = (by * NCHUNK) / KSPLIT;
    const int c1 = ((by + 1) * NCHUNK) / KSPLIT;
    const int n = c1 - c0;

    // --- loader mapping (f32 globals) ---
    const int ar = tid & 127;         // A row
    const int ah = tid >> 7;          // A k-half (32 k each)
    const int grow = rowbase + ar;
    const float* arow = (grow < SUPROWS)
                        ? (sup + (size_t)grow * V_)
                        : (tgt + (size_t)(grow - SUPROWS) * V_);
    uint32_t a_off[4];
    #pragma unroll
    for (int u = 0; u < 4; ++u)
        a_off[u] = (uint32_t)(((ar << 7) | (ah << 6) | (u << 4)) ^ ((ar & 7) << 4));

    const int wd = tid & 63;          // W row (output col d)
    const int wq = tid >> 6;          // W k-quarter (16 k each)
    const float* wrow = W + (size_t)wd * V_;
    uint32_t w_off[2];
    #pragma unroll
    for (int u = 0; u < 2; ++u)
        w_off[u] = (uint32_t)(((wd << 7) | (wq << 5) | (u << 4)) ^ ((wd & 7) << 4));

    // --- ldmatrix per-thread address precompute ---
    const int quad = lane >> 3;
    const int rin = lane & 7;
    uint32_t arow128[2], asw[2];
    #pragma unroll
    for (int m = 0; m < 2; ++m) {
        int row = 32 * wr + 16 * m + (quad & 1) * 8 + rin;
        arow128[m] = (uint32_t)(row << 7);
        asw[m] = (uint32_t)((row & 7) << 4);
    }
    const uint32_t acolq = (uint32_t)((quad >> 1) << 4);
    uint32_t brow128[2], bsw[2];
    #pragma unroll
    for (int p = 0; p < 2; ++p) {
        int row = 32 * wc + 16 * p + (quad >> 1) * 8 + rin;
        brow128[p] = (uint32_t)(row << 7);
        bsw[p] = (uint32_t)((row & 7) << 4);
    }
    const uint32_t bcolq = (uint32_t)((quad & 1) << 4);

    float acc[2][4][4];
    #pragma unroll
    for (int m = 0; m < 2; ++m)
        #pragma unroll
        for (int g = 0; g < 4; ++g)
            #pragma unroll
            for (int j = 0; j < 4; ++j) acc[m][g][j] = 0.f;

    const float4 z4 = make_float4(0.f, 0.f, 0.f, 0.f);
    float4 av[8], wv[4];

    // --- prologue: load + stage chunk c0 into buf0 ---
    {
        const int kbase = c0 * 64;
        #pragma unroll
        for (int j = 0; j < 8; ++j) {
            const int k = kbase + ah * 32 + 4 * j;
            av[j] = (k < V_) ? *(const float4*)(arow + k) : z4;
        }
        #pragma unroll
        for (int j = 0; j < 4; ++j) {
            const int k = kbase + wq * 16 + 4 * j;
            wv[j] = (k < V_) ? *(const float4*)(wrow + k) : z4;
        }
        char* base = smem;
        #pragma unroll
        for (int u = 0; u < 4; ++u) {
            float4 p = av[2 * u], q = av[2 * u + 1];
            uint4 hi, lo;
            hi.x = prmt_hi(p.x, p.y); hi.y = prmt_hi(p.z, p.w);
            hi.z = prmt_hi(q.x, q.y); hi.w = prmt_hi(q.z, q.w);
            lo.x = pack_lo(p.x, p.y); lo.y = pack_lo(p.z, p.w);
            lo.z = pack_lo(q.x, q.y); lo.w = pack_lo(q.z, q.w);
            *(uint4*)(base + A_HI_OFF + a_off[u]) = hi;
            *(uint4*)(base + A_LO_OFF + a_off[u]) = lo;
        }
        #pragma unroll
        for (int u = 0; u < 2; ++u) {
            float4 p = wv[2 * u], q = wv[2 * u + 1];
            uint4 hi, lo;
            hi.x = prmt_hi(p.x, p.y); hi.y = prmt_hi(p.z, p.w);
            hi.z = prmt_hi(q.x, q.y); hi.w = prmt_hi(q.z, q.w);
            lo.x = pack_lo(p.x, p.y); lo.y = pack_lo(p.z, p.w);
            lo.z = pack_lo(q.x, q.y); lo.w = pack_lo(q.z, q.w);
            *(uint4*)(base + W_HI_OFF + w_off[u]) = hi;
            *(uint4*)(base + W_LO_OFF + w_off[u]) = lo;
        }
    }
    __syncthreads();

    for (int i = 0; i < n; ++i) {
        const bool more = (i + 1 < n);
        if (more) {
            const int kbase = (c0 + i + 1) * 64;
            #pragma unroll
            for (int j = 0; j < 8; ++j) {
                const int k = kbase + ah * 32 + 4 * j;
                av[j] = (k < V_) ? *(const float4*)(arow + k) : z4;
            }
            #pragma unroll
            for (int j = 0; j < 4; ++j) {
                const int k = kbase + wq * 16 + 4 * j;
                wv[j] = (k < V_) ? *(const float4*)(wrow + k) : z4;
            }
        }

        // --- compute buf[i&1] : 4 ksteps x (hh, hl, lh) ---
        const uint32_t bufb = sb + (uint32_t)((i & 1) * BUF_STRIDE);
        const uint32_t abh = bufb + A_HI_OFF, abl = bufb + A_LO_OFF;
        const uint32_t wbh = bufb + W_HI_OFF, wbl = bufb + W_LO_OFF;
        #pragma unroll
        for (int ks = 0; ks < 4; ++ks) {
            const uint32_t ac = (uint32_t)(32 * ks) + acolq;
            const uint32_t bc = (uint32_t)(32 * ks) + bcolq;
            uint32_t Ah[2][4], Al[2][4], Bh[2][4], Bl[2][4];
            #pragma unroll
            for (int m = 0; m < 2; ++m) {
                ldsm4(Ah[m], abh + arow128[m] + (ac ^ asw[m]));
                ldsm4(Al[m], abl + arow128[m] + (ac ^ asw[m]));
            }
            #pragma unroll
            for (int p = 0; p < 2; ++p) {
                ldsm4(Bh[p], wbh + brow128[p] + (bc ^ bsw[p]));
                ldsm4(Bl[p], wbl + brow128[p] + (bc ^ bsw[p]));
            }
            #pragma unroll
            for (int m = 0; m < 2; ++m) {
                #pragma unroll
                for (int g = 0; g < 4; ++g) {
                    const int p = g >> 1, h = (g & 1) * 2;
                    mma_bf16(acc[m][g], Ah[m], &Bh[p][h]);
                    mma_bf16(acc[m][g], Ah[m], &Bl[p][h]);
                    mma_bf16(acc[m][g], Al[m], &Bh[p][h]);
                }
            }
        }

        if (more) {
            char* base = smem + ((i + 1) & 1) * BUF_STRIDE;
            #pragma unroll
            for (int u = 0; u < 4; ++u) {
                float4 p = av[2 * u], q = av[2 * u + 1];
                uint4 hi, lo;
                hi.x = prmt_hi(p.x, p.y); hi.y = prmt_hi(p.z, p.w);
                hi.z = prmt_hi(q.x, q.y); hi.w = prmt_hi(q.z, q.w);
                lo.x = pack_lo(p.x, p.y); lo.y = pack_lo(p.z, p.w);
                lo.z = pack_lo(q.x, q.y); lo.w = pack_lo(q.z, q.w);
                *(uint4*)(base + A_HI_OFF + a_off[u]) = hi;
                *(uint4*)(base + A_LO_OFF + a_off[u]) = lo;
            }
            #pragma unroll
            for (int u = 0; u < 2; ++u) {
                float4 p = wv[2 * u], q = wv[2 * u + 1];
                uint4 hi, lo;
                hi.x = prmt_hi(p.x, p.y); hi.y = prmt_hi(p.z, p.w);
                hi.z = prmt_hi(q.x, q.y); hi.w = prmt_hi(q.z, q.w);
                lo.x = pack_lo(p.x, p.y); lo.y = pack_lo(p.z, p.w);
                lo.z = pack_lo(q.x, q.y); lo.w = pack_lo(q.z, q.w);
                *(uint4*)(base + W_HI_OFF + w_off[u]) = hi;
                *(uint4*)(base + W_LO_OFF + w_off[u]) = lo;
            }
            __syncthreads();
        }
    }

    // --- epilogue: acc -> g_Yp ---
    float* yp = g_Yp + ((size_t)by * MROWS + rowbase) * D_;
    #pragma unroll
    for (int m = 0; m < 2; ++m) {
        const int r0 = 32 * wr + 16 * m + (lane >> 2);
        #pragma unroll
        for (int g = 0; g < 4; ++g) {
            const int nn = 32 * wc + 8 * g + 2 * (lane & 3);
            *(float2*)(yp + (size_t)r0 * D_ + nn) =
                make_float2(acc[m][g][0], acc[m][g][1]);
            *(float2*)(yp + (size_t)(r0 + 8) * D_ + nn) =
                make_float2(acc[m][g][2], acc[m][g][3]);
        }
    }
}

// ---------------------------------------------------------------------------
// Head: one warp per batch element.
// ---------------------------------------------------------------------------
__global__ __launch_bounds__(32)
void head_kernel(const float* __restrict__ onehot,
                 const int* __restrict__ tylab,
                 const float* __restrict__ bias) {
    const int b = blockIdx.x;
    const int lane = threadIdx.x;
    const unsigned FULL = 0xffffffffu;

    const float b0 = bias[lane], b1 = bias[lane + 32];

    const int trow = SUPROWS + b;
    float tg0 = b0, tg1 = b1;
    #pragma unroll
    for (int p = 0; p < KSPLIT; ++p) {
        const float* r = g_Yp + ((size_t)p * MROWS + trow) * D_;
        tg0 += r[lane]; tg1 += r[lane + 32];
    }

    float sims[S_];
    #pragma unroll
    for (int s = 0; s < S_; ++s) {
        const int row = b * S_ + s;
        float v0 = b0, v1 = b1;
        #pragma unroll
        for (int p = 0; p < KSPLIT; ++p) {
            const float* r = g_Yp + ((size_t)p * MROWS + row) * D_;
            v0 += r[lane]; v1 += r[lane + 32];
        }
        float dot = v0 * tg0 + v1 * tg1;
        float nrm = v0 * v0 + v1 * v1;
        #pragma unroll
        for (int o = 16; o > 0; o >>= 1) {
            dot += __shfl_xor_sync(FULL, dot, o);
            nrm += __shfl_xor_sync(FULL, nrm, o);
        }
        sims[s] = dot * rsqrtf(fmaxf(nrm, 1e-10f));
    }

    float m = sims[0];
    #pragma unroll
    for (int s = 1; s < S_; ++s) m = fmaxf(m, sims[s]);
    float e[S_];
    float den = 0.f;
    #pragma unroll
    for (int s = 0; s < S_; ++s) { e[s] = expf(sims[s] - m); den += e[s]; }
    const float inv = 1.f / den;

    float pred = 0.f;
    if (lane < C_) {
        #pragma unroll
        for (int s = 0; s < S_; ++s)
            pred += e[s] * inv * onehot[((size_t)b * S_ + s) * C_ + lane];
    }

    float pv = (lane < C_) ? pred : -3.0e38f;
    float pm = pv;
    #pragma unroll
    for (int o = 16; o > 0; o >>= 1) pm = fmaxf(pm, __shfl_xor_sync(FULL, pm, o));
    float ex = (lane < C_) ? expf(pred - pm) : 0.f;
    float se = ex;
    #pragma unroll
    for (int o = 16; o > 0; o >>= 1) se += __shfl_xor_sync(FULL, se, o);
    const float lse = pm + logf(se);

    float av = pv;
    int ai = lane;
    #pragma unroll
    for (int o = 16; o > 0; o >>= 1) {
        float ov = __shfl_xor_sync(FULL, av, o);
        int oi = __shfl_xor_sync(FULL, ai, o);
        if (ov > av || (ov == av && oi < ai)) { av = ov; ai = oi; }
    }

    const int t = tylab[b];
    const float pt = __shfl_sync(FULL, pred, t);
    if (lane == 0) {
        g_res[b] = (ai == t) ? 1.f : 0.f;
        g_res[B_ + b] = -(pt - lse);
    }
}

// ---------------------------------------------------------------------------
// Final fixed-order reduction -> d_out[0]=accuracy, d_out[1]=loss
// ---------------------------------------------------------------------------
__global__ __launch_bounds__(256)
void reduce_kernel(float* __restrict__ out) {
    __shared__ float s0[B_], s1[B_];
    const int t = threadIdx.x;
    s0[t] = g_res[t];
    s1[t] = g_res[B_ + t];
    __syncthreads();
    #pragma unroll
    for (int o = 128; o > 0; o >>= 1) {
        if (t < o) { s0[t] += s0[t + o]; s1[t] += s1[t + o]; }
        __syncthreads();
    }
    if (t == 0) {
        out[0] = s0[0] * (1.f / B_);
        out[1] = s1[0] * (1.f / B_);
    }
}

extern "C" void kernel_launch(void* const* d_in, const int* in_sizes, int n_in,
                              void* d_out, int out_size) {
    const float* sup    = (const float*)d_in[0];
    const float* onehot = (const float*)d_in[1];
    const float* tgt    = (const float*)d_in[2];
    const int*   tylab  = (const int*)d_in[3];
    const float* W      = (const float*)d_in[4];
    const float* bias   = (const float*)d_in[5];
    (void)in_sizes; (void)n_in; (void)out_size;

    cudaFuncSetAttribute(gemm_kernel,
                         cudaFuncAttributeMaxDynamicSharedMemorySize, SMEM_TOTAL);

    dim3 grid(MROWS / TILE_R, KSPLIT);
    gemm_kernel<<<grid, 256, SMEM_TOTAL>>>(sup, tgt, W);
    head_kernel<<<B_, 32>>>(onehot, tylab, bias);
    reduce_kernel<<<1, 256>>>((float*)d_out);
}